// round 13
// baseline (speedup 1.0000x reference)
#include <cuda_runtime.h>
#include <math.h>

#define cB 64
#define cL 256
#define cE 256
#define cH 512
#define cM 256
#define cHD 64
#define cO 1024
#define cCI 512
#define cTO 768
#define EPS 1e-5f
#define NBLK 256
#define SCRF 2848

typedef unsigned long long ull;

__device__ float g_h[2][cB][cH];
__device__ float g_c[cB][cH];
__device__ float g_ci[cB][cCI];
__device__ float g_outln[2][cB][cTO];
__device__ float g_head[cB][512];
__device__ float g_gpart[2][cB][2048];
__device__ float g_lnpart[2][cB][2];
__device__ unsigned g_cnt = 0;
__device__ unsigned g_gen = 0;

__device__ __forceinline__ float sigf(float x) { return 1.0f / (1.0f + expf(-x)); }

__device__ __forceinline__ ull dup2(float w) {
    ull r;
    asm("mov.b64 %0, {%1, %1};" : "=l"(r) : "f"(w));
    return r;
}
__device__ __forceinline__ void ffma2(ull& acc, ull a, ull b) {
    asm("fma.rn.f32x2 %0, %1, %2, %0;" : "+l"(acc) : "l"(a), "l"(b));
}
__device__ __forceinline__ float2 unpk(ull v) {
    float2 r;
    asm("mov.b64 {%0, %1}, %2;" : "=f"(r.x), "=f"(r.y) : "l"(v));
    return r;
}

__device__ __forceinline__ void gsync() {
    __syncthreads();
    if (threadIdx.x == 0) {
        unsigned gen = *(volatile unsigned*)&g_gen;
        __threadfence();
        if (atomicAdd(&g_cnt, 1u) == NBLK - 1) {
            g_cnt = 0;
            __threadfence();
            *(volatile unsigned*)&g_gen = gen + 1;
        } else {
            while (*(volatile unsigned*)&g_gen == gen) {}
        }
        __threadfence();
    }
    __syncthreads();
}

__device__ __forceinline__ float brsum(float v, float* red) {
    int tid = threadIdx.x;
#pragma unroll
    for (int o = 16; o; o >>= 1) v += __shfl_xor_sync(0xffffffffu, v, o);
    if ((tid & 31) == 0) red[tid >> 5] = v;
    __syncthreads();
    if (tid == 0) { float s = 0.f; for (int i = 0; i < 8; ++i) s += red[i]; red[0] = s; }
    __syncthreads();
    float r = red[0];
    __syncthreads();
    return r;
}
__device__ __forceinline__ float brmax(float v, float* red) {
    int tid = threadIdx.x;
#pragma unroll
    for (int o = 16; o; o >>= 1) v = fmaxf(v, __shfl_xor_sync(0xffffffffu, v, o));
    if ((tid & 31) == 0) red[tid >> 5] = v;
    __syncthreads();
    if (tid == 0) { float s = red[0]; for (int i = 1; i < 8; ++i) s = fmaxf(s, red[i]); red[0] = s; }
    __syncthreads();
    float r = red[0];
    __syncthreads();
    return r;
}

__device__ __forceinline__ const float* headrow(int g, const float* Wrk, const float* Wwk,
                                                const float* Wws, const float* Wer,
                                                const float* Wad) {
    if (g < 256) return Wrk + (size_t)g * 512;
    if (g < 320) return Wwk + (size_t)(g - 256) * 512;
    if (g == 320) return Wws;
    if (g < 385) return Wer + (size_t)(g - 321) * 512;
    if (g < 449) return Wad + (size_t)(g - 385) * 512;
    return nullptr;
}

// phase A: split-K2 gates GEMM partial: block = (kc, 16-col group), 64x16 over K=512
__device__ void doA(int t, float* scr, const float* __restrict__ Wih,
                    const float* __restrict__ Whh) {
    int tid = threadIdx.x, bx = blockIdx.x;
    int kc = bx & 1, jj = bx >> 1;
    int n0g = jj * 16, cur = t & 1;
    const float* Abase = kc ? &g_h[cur][0][0] : &g_ci[0][0];
    const float* Wbase = kc ? Whh : Wih;
    float* As = scr;          // [32][66]
    float* Ws = scr + 2112;   // [32][16]
    int mt = tid >> 3, nt = tid & 7;
    int am0 = tid >> 3, ak = (tid & 7) * 4, am1 = am0 + 32;
    int wc = tid >> 3, wk = (tid & 7) * 4;
    ull acc0 = 0ull, acc1 = 0ull;
    float4 va0, va1, vw = make_float4(0.f, 0.f, 0.f, 0.f);
    va0 = *(const float4*)(Abase + am0 * 512 + ak);
    va1 = *(const float4*)(Abase + am1 * 512 + ak);
    if (tid < 128) vw = *(const float4*)(Wbase + (size_t)(n0g + wc) * 512 + wk);
    for (int kt = 0; kt < 512; kt += 32) {
        __syncthreads();
        As[(ak + 0) * 66 + am0] = va0.x; As[(ak + 1) * 66 + am0] = va0.y;
        As[(ak + 2) * 66 + am0] = va0.z; As[(ak + 3) * 66 + am0] = va0.w;
        As[(ak + 0) * 66 + am1] = va1.x; As[(ak + 1) * 66 + am1] = va1.y;
        As[(ak + 2) * 66 + am1] = va1.z; As[(ak + 3) * 66 + am1] = va1.w;
        if (tid < 128) {
            Ws[(wk + 0) * 16 + wc] = vw.x; Ws[(wk + 1) * 16 + wc] = vw.y;
            Ws[(wk + 2) * 16 + wc] = vw.z; Ws[(wk + 3) * 16 + wc] = vw.w;
        }
        if (kt + 32 < 512) {
            va0 = *(const float4*)(Abase + am0 * 512 + kt + 32 + ak);
            va1 = *(const float4*)(Abase + am1 * 512 + kt + 32 + ak);
            if (tid < 128)
                vw = *(const float4*)(Wbase + (size_t)(n0g + wc) * 512 + kt + 32 + wk);
        }
        __syncthreads();
#pragma unroll
        for (int k = 0; k < 32; ++k) {
            ull a = *(const ull*)&As[k * 66 + mt * 2];
            float2 w = *(const float2*)&Ws[k * 16 + nt * 2];
            ffma2(acc0, a, dup2(w.x));
            ffma2(acc1, a, dup2(w.y));
        }
    }
    float2 r0 = unpk(acc0), r1 = unpk(acc1);
    float* gp = &g_gpart[kc][0][0];
    int col = n0g + 2 * nt;
    *(float2*)&gp[(size_t)(2 * mt) * 2048 + col] = make_float2(r0.x, r1.x);
    *(float2*)&gp[(size_t)(2 * mt + 1) * 2048 + col] = make_float2(r0.y, r1.y);
}

// phase A2 (blocks 0..127): LSTM cell update + LN partials, one cell per thread
__device__ void doA2(int t, float* scr, const float* __restrict__ bih,
                     const float* __restrict__ bhh) {
    int tid = threadIdx.x, bx = blockIdx.x;
    int b = bx >> 1, u = (bx & 1) * 256 + tid;
    int nx = (t + 1) & 1;
    float gi = g_gpart[0][b][u] + g_gpart[1][b][u] + bih[u] + bhh[u];
    float gf = g_gpart[0][b][512 + u] + g_gpart[1][b][512 + u] + bih[512 + u] + bhh[512 + u];
    float gg = g_gpart[0][b][1024 + u] + g_gpart[1][b][1024 + u] + bih[1024 + u] + bhh[1024 + u];
    float go = g_gpart[0][b][1536 + u] + g_gpart[1][b][1536 + u] + bih[1536 + u] + bhh[1536 + u];
    float cc = sigf(gf) * g_c[b][u] + sigf(gi) * tanhf(gg);
    float hh = sigf(go) * tanhf(cc);
    g_c[b][u] = cc;
    g_h[nx][b][u] = hh;
    float s = brsum(hh, scr);
    float s2 = brsum(hh * hh, scr);
    if (tid == 0) { g_lnpart[bx & 1][b][0] = s; g_lnpart[bx & 1][b][1] = s2; }
}

// phase B (blocks 0..127): heads GEMM, 4 cols per block, LN(h) inline
__device__ void doHeads(int q, int nx, float* scr,
                        const float* __restrict__ lnhg, const float* __restrict__ lnhb,
                        const float* __restrict__ Wrk, const float* __restrict__ Wwk,
                        const float* __restrict__ Wws, const float* __restrict__ Wer,
                        const float* __restrict__ Wad) {
    int tid = threadIdx.x;
    float* As = scr;           // [32][66]
    float* Ws = scr + 2112;    // [32][4]
    float* smean = scr + 2304; // 64
    float* srstd = scr + 2368; // 64
    if (tid < 64) {
        float s = g_lnpart[0][tid][0] + g_lnpart[1][tid][0];
        float s2 = g_lnpart[0][tid][1] + g_lnpart[1][tid][1];
        float m = s * (1.f / 512);
        smean[tid] = m;
        srstd[tid] = rsqrtf(s2 * (1.f / 512) - m * m + EPS);
    }
    __syncthreads();
    int m = tid >> 2, c = tid & 3;
    int ar0 = tid >> 3, ar1 = ar0 + 32, ak = (tid & 7) * 4;
    const float* wp = headrow(q * 4 + (tid >> 3), Wrk, Wwk, Wws, Wer, Wad);
    float acc = 0.f;
    float4 hv0, hv1, gv0, bv0, vwh = make_float4(0.f, 0.f, 0.f, 0.f);
    hv0 = *(const float4*)&g_h[nx][ar0][ak];
    hv1 = *(const float4*)&g_h[nx][ar1][ak];
    gv0 = *(const float4*)&lnhg[ak];
    bv0 = *(const float4*)&lnhb[ak];
    if (tid < 32 && wp) vwh = *(const float4*)(wp + ((tid & 7) * 4));
    for (int kt = 0; kt < 512; kt += 32) {
        __syncthreads();
        {
            float mm = smean[ar0], rs = srstd[ar0];
            As[(ak + 0) * 66 + ar0] = (hv0.x - mm) * rs * gv0.x + bv0.x;
            As[(ak + 1) * 66 + ar0] = (hv0.y - mm) * rs * gv0.y + bv0.y;
            As[(ak + 2) * 66 + ar0] = (hv0.z - mm) * rs * gv0.z + bv0.z;
            As[(ak + 3) * 66 + ar0] = (hv0.w - mm) * rs * gv0.w + bv0.w;
            mm = smean[ar1]; rs = srstd[ar1];
            As[(ak + 0) * 66 + ar1] = (hv1.x - mm) * rs * gv0.x + bv0.x;
            As[(ak + 1) * 66 + ar1] = (hv1.y - mm) * rs * gv0.y + bv0.y;
            As[(ak + 2) * 66 + ar1] = (hv1.z - mm) * rs * gv0.z + bv0.z;
            As[(ak + 3) * 66 + ar1] = (hv1.w - mm) * rs * gv0.w + bv0.w;
        }
        if (tid < 32) {
            int c2 = tid >> 3, kq = (tid & 7) * 4;
            Ws[(kq + 0) * 4 + c2] = vwh.x; Ws[(kq + 1) * 4 + c2] = vwh.y;
            Ws[(kq + 2) * 4 + c2] = vwh.z; Ws[(kq + 3) * 4 + c2] = vwh.w;
        }
        if (kt + 32 < 512) {
            hv0 = *(const float4*)&g_h[nx][ar0][kt + 32 + ak];
            hv1 = *(const float4*)&g_h[nx][ar1][kt + 32 + ak];
            gv0 = *(const float4*)&lnhg[kt + 32 + ak];
            bv0 = *(const float4*)&lnhb[kt + 32 + ak];
            if (tid < 32 && wp) vwh = *(const float4*)(wp + kt + 32 + ((tid & 7) * 4));
        }
        __syncthreads();
#pragma unroll
        for (int k = 0; k < 32; ++k) acc += As[k * 66 + m] * Ws[k * 4 + c];
    }
    g_head[m][q * 4 + c] = acc;
}

// phase B (blocks 128..191): proj, 16 cols per block, K=768
__device__ void doProj(int p, int trow, float* scr, const float* __restrict__ Aouts,
                       const float* __restrict__ Wproj, const float* __restrict__ bproj,
                       float* __restrict__ out) {
    int tid = threadIdx.x;
    float* As = scr;          // [32][68]
    float* Ws = scr + 2176;   // [32][20]
    int r0 = (tid >> 3) * 2, c0 = (tid & 7) * 2;
    int ar0 = tid >> 3, ar1 = ar0 + 32, ak = (tid & 7) * 4;
    int wc = tid >> 3, wk = (tid & 7) * 4;
    float a00 = 0.f, a01 = 0.f, a10 = 0.f, a11 = 0.f;
    float4 va0, va1, vw = make_float4(0.f, 0.f, 0.f, 0.f);
    va0 = *(const float4*)&Aouts[ar0 * 768 + ak];
    va1 = *(const float4*)&Aouts[ar1 * 768 + ak];
    if (tid < 128) vw = *(const float4*)&Wproj[(size_t)(16 * p + wc) * 768 + wk];
    for (int kt = 0; kt < 768; kt += 32) {
        __syncthreads();
        As[(ak + 0) * 68 + ar0] = va0.x; As[(ak + 1) * 68 + ar0] = va0.y;
        As[(ak + 2) * 68 + ar0] = va0.z; As[(ak + 3) * 68 + ar0] = va0.w;
        As[(ak + 0) * 68 + ar1] = va1.x; As[(ak + 1) * 68 + ar1] = va1.y;
        As[(ak + 2) * 68 + ar1] = va1.z; As[(ak + 3) * 68 + ar1] = va1.w;
        if (tid < 128) {
            Ws[(wk + 0) * 20 + wc] = vw.x; Ws[(wk + 1) * 20 + wc] = vw.y;
            Ws[(wk + 2) * 20 + wc] = vw.z; Ws[(wk + 3) * 20 + wc] = vw.w;
        }
        if (kt + 32 < 768) {
            va0 = *(const float4*)&Aouts[ar0 * 768 + kt + 32 + ak];
            va1 = *(const float4*)&Aouts[ar1 * 768 + kt + 32 + ak];
            if (tid < 128)
                vw = *(const float4*)&Wproj[(size_t)(16 * p + wc) * 768 + kt + 32 + wk];
        }
        __syncthreads();
#pragma unroll
        for (int k = 0; k < 32; ++k) {
            float2 a = *(const float2*)&As[k * 68 + r0];
            float2 w = *(const float2*)&Ws[k * 20 + c0];
            a00 += a.x * w.x; a01 += a.x * w.y; a10 += a.y * w.x; a11 += a.y * w.y;
        }
    }
    int col = 16 * p + c0;
    float b0 = bproj[col], b1 = bproj[col + 1];
    out[((size_t)(r0 + 0) * cL + trow) * cO + col]     = a00 + b0;
    out[((size_t)(r0 + 0) * cL + trow) * cO + col + 1] = a01 + b1;
    out[((size_t)(r0 + 1) * cL + trow) * cO + col]     = a10 + b0;
    out[((size_t)(r0 + 1) * cL + trow) * cO + col + 1] = a11 + b1;
}

// phase C (blocks 0..63): memory write/read + outln + next ci
__device__ void doMem(int t, int b, float* s_mem, float* scr, const float* __restrict__ x,
                      const float* __restrict__ brk, const float* __restrict__ bwk,
                      const float* __restrict__ bws, const float* __restrict__ ber,
                      const float* __restrict__ bad,
                      const float* __restrict__ lnhg, const float* __restrict__ lnhb,
                      const float* __restrict__ lnrkg, const float* __restrict__ lnrkb,
                      const float* __restrict__ lnwkg, const float* __restrict__ lnwkb,
                      const float* __restrict__ lnmg, const float* __restrict__ lnmb,
                      const float* __restrict__ lnog, const float* __restrict__ lnob,
                      const float* __restrict__ lning, const float* __restrict__ lninb) {
    float* s_hn = scr;           // 512
    float* s_rk = scr + 512;     // 256
    float* s_wk = scr + 768;     // 64
    float* s_er = scr + 832;     // 64
    float* s_ad = scr + 896;     // 64
    float* s_wkln = scr + 960;   // 64
    float* s_rkln = scr + 1024;  // 256
    float* s_wsc = scr + 1280;   // 256
    float* s_rsc = scr + 1536;   // 1024
    float* s_rv = scr + 2560;    // 256
    float* red = scr + 2816;     // 8
    float* misc = scr + 2824;    // 4
    int tid = threadIdx.x, warp = tid >> 5, lane = tid & 31;
    int nx = (t + 1) & 1, ob = t & 1;

    if (tid == 0) {
        float s = g_lnpart[0][b][0] + g_lnpart[1][b][0];
        float s2 = g_lnpart[0][b][1] + g_lnpart[1][b][1];
        float m = s * (1.f / 512);
        misc[1] = m;
        misc[2] = rsqrtf(s2 * (1.f / 512) - m * m + EPS);
    }
    __syncthreads();
    float hm = misc[1], hrs = misc[2];
#pragma unroll
    for (int u = 0; u < 2; ++u) {
        int k = tid + u * 256;
        s_hn[k] = (g_h[nx][b][k] - hm) * hrs * lnhg[k] + lnhb[k];
    }
    for (int j = tid; j < 449; j += 256) {
        float v = g_head[b][j];
        if (j < 256) s_rk[j] = v + brk[j];
        else if (j < 320) s_wk[j - 256] = v + bwk[j - 256];
        else if (j == 320) misc[0] = sigf(v + bws[0]);
        else if (j < 385) s_er[j - 321] = sigf(v + ber[j - 321]);
        else s_ad[j - 385] = tanhf(v + bad[j - 385]);
    }
    __syncthreads();
    if (warp == 0) {
        float x0 = s_wk[lane], x1 = s_wk[lane + 32], s = x0 + x1;
#pragma unroll
        for (int o = 16; o; o >>= 1) s += __shfl_xor_sync(0xffffffffu, s, o);
        float mean = s * (1.f / 64), d0 = x0 - mean, d1 = x1 - mean;
        float vs = d0 * d0 + d1 * d1;
#pragma unroll
        for (int o = 16; o; o >>= 1) vs += __shfl_xor_sync(0xffffffffu, vs, o);
        float rs = rsqrtf(vs * (1.f / 64) + EPS);
        s_wkln[lane] = d0 * rs * lnwkg[lane] + lnwkb[lane];
        s_wkln[lane + 32] = d1 * rs * lnwkg[lane + 32] + lnwkb[lane + 32];
    } else if (warp <= 4) {
        int r = warp - 1;
        float x0 = s_rk[r * 64 + lane], x1 = s_rk[r * 64 + lane + 32], s = x0 + x1;
#pragma unroll
        for (int o = 16; o; o >>= 1) s += __shfl_xor_sync(0xffffffffu, s, o);
        float mean = s * (1.f / 64), d0 = x0 - mean, d1 = x1 - mean;
        float vs = d0 * d0 + d1 * d1;
#pragma unroll
        for (int o = 16; o; o >>= 1) vs += __shfl_xor_sync(0xffffffffu, vs, o);
        float rs = rsqrtf(vs * (1.f / 64) + EPS);
        s_rkln[r * 64 + lane] = d0 * rs * lnrkg[lane] + lnrkb[lane];
        s_rkln[r * 64 + lane + 32] = d1 * rs * lnrkg[lane + 32] + lnrkb[lane + 32];
    }
    __syncthreads();
    float mg0 = lnmg[lane], mg1 = lnmg[lane + 32];
    float mb0 = lnmb[lane], mb1 = lnmb[lane + 32];
    float wkl0 = s_wkln[lane], wkl1 = s_wkln[lane + 32];
    for (int m = warp; m < cM; m += 8) {
        float x0 = s_mem[m * 64 + lane], x1 = s_mem[m * 64 + lane + 32], s = x0 + x1;
#pragma unroll
        for (int o = 16; o; o >>= 1) s += __shfl_xor_sync(0xffffffffu, s, o);
        float mean = s * (1.f / 64), d0 = x0 - mean, d1 = x1 - mean;
        float vs = d0 * d0 + d1 * d1;
#pragma unroll
        for (int o = 16; o; o >>= 1) vs += __shfl_xor_sync(0xffffffffu, vs, o);
        float rs = rsqrtf(vs * (1.f / 64) + EPS);
        float dot = (d0 * rs * mg0 + mb0) * wkl0 + (d1 * rs * mg1 + mb1) * wkl1;
#pragma unroll
        for (int o = 16; o; o >>= 1) dot += __shfl_xor_sync(0xffffffffu, dot, o);
        if (lane == 0) s_wsc[m] = dot;
    }
    __syncthreads();
    {
        float v = s_wsc[tid];
        float mx = brmax(v, red);
        float e = expf(v - mx);
        float su = brsum(e, red);
        s_wsc[tid] = e / su * misc[0];
    }
    __syncthreads();
    for (int i = tid; i < cM * cHD; i += 256) {
        int m = i >> 6, hh = i & 63;
        float w = s_wsc[m];
        s_mem[i] = s_mem[i] * (1.f - w * s_er[hh]) + w * s_ad[hh];
    }
    __syncthreads();
    for (int m = warp; m < cM; m += 8) {
        float x0 = s_mem[m * 64 + lane], x1 = s_mem[m * 64 + lane + 32], s = x0 + x1;
#pragma unroll
        for (int o = 16; o; o >>= 1) s += __shfl_xor_sync(0xffffffffu, s, o);
        float mean = s * (1.f / 64), d0 = x0 - mean, d1 = x1 - mean;
        float vs = d0 * d0 + d1 * d1;
#pragma unroll
        for (int o = 16; o; o >>= 1) vs += __shfl_xor_sync(0xffffffffu, vs, o);
        float rs = rsqrtf(vs * (1.f / 64) + EPS);
        float n0 = d0 * rs * mg0 + mb0, n1 = d1 * rs * mg1 + mb1;
#pragma unroll
        for (int r = 0; r < 4; ++r) {
            float a = n0 * s_rkln[r * 64 + lane] + n1 * s_rkln[r * 64 + lane + 32];
#pragma unroll
            for (int o = 16; o; o >>= 1) a += __shfl_xor_sync(0xffffffffu, a, o);
            if (lane == 0) s_rsc[r * 256 + m] = a;
        }
    }
    __syncthreads();
#pragma unroll
    for (int r = 0; r < 4; ++r) {
        float v = s_rsc[r * 256 + tid];
        float mx = brmax(v, red);
        float e = expf(v - mx);
        float su = brsum(e, red);
        s_rsc[r * 256 + tid] = e / su;
    }
    __syncthreads();
    {
        int r = tid >> 6, hh = tid & 63;
        float a0 = 0.f, a1 = 0.f, a2 = 0.f, a3 = 0.f;
#pragma unroll 4
        for (int m = 0; m < cM; m += 4) {
            a0 += s_rsc[r * 256 + m + 0] * s_mem[(m + 0) * 64 + hh];
            a1 += s_rsc[r * 256 + m + 1] * s_mem[(m + 1) * 64 + hh];
            a2 += s_rsc[r * 256 + m + 2] * s_mem[(m + 2) * 64 + hh];
            a3 += s_rsc[r * 256 + m + 3] * s_mem[(m + 3) * 64 + hh];
        }
        s_rv[tid] = (a0 + a1) + (a2 + a3);
    }
    __syncthreads();
    {
        float o0 = s_hn[tid], o1 = s_hn[tid + 256], o2 = s_rv[tid];
        float mean = brsum(o0 + o1 + o2, red) * (1.f / cTO);
        float d0 = o0 - mean, d1 = o1 - mean, d2 = o2 - mean;
        float var = brsum(d0 * d0 + d1 * d1 + d2 * d2, red) * (1.f / cTO);
        float rs = rsqrtf(var + EPS);
        g_outln[ob][b][tid] = d0 * rs * lnog[tid] + lnob[tid];
        g_outln[ob][b][tid + 256] = d1 * rs * lnog[tid + 256] + lnob[tid + 256];
        g_outln[ob][b][tid + 512] = d2 * rs * lnog[tid + 512] + lnob[tid + 512];
    }
    if (t + 1 < cL) {
        const float* xn = x + ((size_t)b * cL + t + 1) * cE;
        float a0 = xn[tid], a1 = s_rv[tid];
        float mean = brsum(a0 + a1, red) * (1.f / cCI);
        float d0 = a0 - mean, d1 = a1 - mean;
        float var = brsum(d0 * d0 + d1 * d1, red) * (1.f / cCI);
        float rs = rsqrtf(var + EPS);
        g_ci[b][tid] = d0 * rs * lning[tid] + lninb[tid];
        g_ci[b][tid + 256] = d1 * rs * lning[tid + 256] + lninb[tid + 256];
    }
}

__global__ void __launch_bounds__(256, 2) k_persist(
    const float* __restrict__ x, const float* __restrict__ Wih,
    const float* __restrict__ Whh, const float* __restrict__ bih,
    const float* __restrict__ bhh, const float* __restrict__ lning,
    const float* __restrict__ lninb, const float* __restrict__ lnhg,
    const float* __restrict__ lnhb, const float* __restrict__ Wrk,
    const float* __restrict__ brk, const float* __restrict__ Wwk,
    const float* __restrict__ bwk, const float* __restrict__ Wws,
    const float* __restrict__ bws, const float* __restrict__ Wer,
    const float* __restrict__ ber, const float* __restrict__ Wad,
    const float* __restrict__ bad, const float* __restrict__ lnrkg,
    const float* __restrict__ lnrkb, const float* __restrict__ lnwkg,
    const float* __restrict__ lnwkb, const float* __restrict__ lnmg,
    const float* __restrict__ lnmb, const float* __restrict__ lnog,
    const float* __restrict__ lnob, const float* __restrict__ Wproj,
    const float* __restrict__ bproj, float* __restrict__ out,
    float* __restrict__ memg, float* __restrict__ hout, float* __restrict__ cout) {
    extern __shared__ float sm[];
    float* s_mem = sm;          // 16384 (persistent memory, blocks 0..63)
    float* scr = sm + 16384;    // SCRF-16384... scratch (2848 floats)
    int bx = blockIdx.x, tid = threadIdx.x;

    if (bx < 64) {
        for (int i = tid; i < cM * cHD; i += 256) s_mem[i] = 0.f;
        int b = bx;
#pragma unroll
        for (int u = 0; u < 2; ++u) {
            int k = tid + u * 256;
            g_c[b][k] = 0.f;
            g_h[0][b][k] = 0.f;
        }
        float* red = scr;
        float a0 = x[(size_t)b * cL * cE + tid];
        float mean = brsum(a0, red) * (1.f / cCI);
        float d0 = a0 - mean, d1 = -mean;
        float var = brsum(d0 * d0 + d1 * d1, red) * (1.f / cCI);
        float rs = rsqrtf(var + EPS);
        g_ci[b][tid] = d0 * rs * lning[tid] + lninb[tid];
        g_ci[b][tid + 256] = d1 * rs * lning[tid + 256] + lninb[tid + 256];
    }
    gsync();

    for (int t = 0; t < cL; ++t) {
        doA(t, scr, Wih, Whh);
        gsync();
        if (bx < 128) doA2(t, scr, bih, bhh);
        gsync();
        if (bx < 128) {
            doHeads(bx, (t + 1) & 1, scr, lnhg, lnhb, Wrk, Wwk, Wws, Wer, Wad);
        } else if (bx < 192 && t > 0) {
            doProj(bx - 128, t - 1, scr, &g_outln[(t - 1) & 1][0][0], Wproj, bproj, out);
        }
        gsync();
        if (bx < 64) {
            doMem(t, bx, s_mem, scr, x, brk, bwk, bws, ber, bad, lnhg, lnhb,
                  lnrkg, lnrkb, lnwkg, lnwkb, lnmg, lnmb, lnog, lnob, lning, lninb);
        }
        gsync();
    }
    if (bx >= 128 && bx < 192) {
        doProj(bx - 128, cL - 1, scr, &g_outln[(cL - 1) & 1][0][0], Wproj, bproj, out);
    } else if (bx < 64) {
        int b = bx;
        for (int i = tid; i < cM * cHD; i += 256) memg[(size_t)b * cM * cHD + i] = s_mem[i];
#pragma unroll
        for (int u = 0; u < 2; ++u) {
            int k = tid + u * 256;
            hout[b * cH + k] = g_h[0][b][k];
            cout[b * cH + k] = g_c[b][k];
        }
    }
}

extern "C" void kernel_launch(void* const* d_in, const int* in_sizes, int n_in,
                              void* d_out, int out_size) {
    const float** p = (const float**)d_in;
    float* out = (float*)d_out;
    float* memg = out + (size_t)cB * cL * cO;
    float* hout = memg + (size_t)cB * cM * cHD;
    float* cout = hout + (size_t)cB * cH;
    const int smem = (16384 + SCRF) * 4;
    cudaFuncSetAttribute(k_persist, cudaFuncAttributeMaxDynamicSharedMemorySize, smem);
    k_persist<<<NBLK, 256, smem>>>(p[0], p[1], p[2], p[3], p[4], p[5], p[6], p[7], p[8],
                                   p[9], p[10], p[11], p[12], p[13], p[14], p[15], p[16],
                                   p[17], p[18], p[19], p[20], p[21], p[22], p[23], p[24],
                                   p[25], p[26], p[27], p[28], out, memg, hout, cout);
}

// round 14
// speedup vs baseline: 1.1894x; 1.1894x over previous
#include <cuda_runtime.h>
#include <math.h>

#define cB 64
#define cL 256
#define cE 256
#define cH 512
#define cM 256
#define cHD 64
#define cO 1024
#define cCI 512
#define cTO 768
#define EPS 1e-5f
#define NBLK 128

typedef unsigned long long ull;

__device__ float g_h[2][cB][cH];
__device__ float g_c[cB][cH];
__device__ float g_ci[cB][cCI];
__device__ float g_outln[2][cB][cTO];
__device__ float g_head[cB][512];
__device__ float g_lnpart[128][cB][2];
__device__ unsigned g_cnt = 0;
__device__ unsigned g_gen = 0;

__device__ __forceinline__ float sigf(float x) { return 1.0f / (1.0f + expf(-x)); }

__device__ __forceinline__ ull dup2(float w) {
    ull r;
    asm("mov.b64 %0, {%1, %1};" : "=l"(r) : "f"(w));
    return r;
}
__device__ __forceinline__ void ffma2(ull& acc, ull a, ull b) {
    asm("fma.rn.f32x2 %0, %1, %2, %0;" : "+l"(acc) : "l"(a), "l"(b));
}
__device__ __forceinline__ float2 unpk(ull v) {
    float2 r;
    asm("mov.b64 {%0, %1}, %2;" : "=f"(r.x), "=f"(r.y) : "l"(v));
    return r;
}

// CG-style grid barrier: acq_rel arrive + acquire spin. NO __threadfence -> no
// CCTL.IVALL -> L1 (weights) stays warm across steps. All cross-block data is
// moved with __ldcg/__stcg (L2 scope) so it never depends on L1 coherence.
__device__ __forceinline__ void gsync() {
    __syncthreads();
    if (threadIdx.x == 0) {
        unsigned gen;
        asm volatile("ld.relaxed.gpu.global.u32 %0, [%1];" : "=r"(gen) : "l"(&g_gen));
        unsigned prev;
        asm volatile("atom.acq_rel.gpu.global.add.u32 %0, [%1], %2;"
                     : "=r"(prev) : "l"(&g_cnt), "r"(1u) : "memory");
        if (prev == NBLK - 1) {
            asm volatile("st.relaxed.gpu.global.u32 [%0], %1;" :: "l"(&g_cnt), "r"(0u) : "memory");
            asm volatile("st.release.gpu.global.u32 [%0], %1;" :: "l"(&g_gen), "r"(gen + 1u) : "memory");
        } else {
            unsigned cur;
            do {
                asm volatile("ld.acquire.gpu.global.u32 %0, [%1];" : "=r"(cur) : "l"(&g_gen) : "memory");
            } while (cur == gen);
        }
    }
    __syncthreads();
}

__device__ __forceinline__ float brsum(float v, float* red) {
    int tid = threadIdx.x;
#pragma unroll
    for (int o = 16; o; o >>= 1) v += __shfl_xor_sync(0xffffffffu, v, o);
    if ((tid & 31) == 0) red[tid >> 5] = v;
    __syncthreads();
    if (tid == 0) { float s = 0.f; for (int i = 0; i < 8; ++i) s += red[i]; red[0] = s; }
    __syncthreads();
    float r = red[0];
    __syncthreads();
    return r;
}
__device__ __forceinline__ float brmax(float v, float* red) {
    int tid = threadIdx.x;
#pragma unroll
    for (int o = 16; o; o >>= 1) v = fmaxf(v, __shfl_xor_sync(0xffffffffu, v, o));
    if ((tid & 31) == 0) red[tid >> 5] = v;
    __syncthreads();
    if (tid == 0) { float s = red[0]; for (int i = 1; i < 8; ++i) s = fmaxf(s, red[i]); red[0] = s; }
    __syncthreads();
    float r = red[0];
    __syncthreads();
    return r;
}

__device__ __forceinline__ const float* headrow(int g, const float* Wrk, const float* Wwk,
                                                const float* Wws, const float* Wer,
                                                const float* Wad) {
    if (g < 256) return Wrk + (size_t)g * 512;
    if (g < 320) return Wwk + (size_t)(g - 256) * 512;
    if (g == 320) return Wws;
    if (g < 385) return Wer + (size_t)(g - 321) * 512;
    if (g < 449) return Wad + (size_t)(g - 385) * 512;
    return nullptr;
}

// phase A: gates GEMM [64 x 16cols, K=1024] f32x2 + fused LSTM (4 units/block)
__device__ void doA(int t, float* scr, const float* __restrict__ Wih,
                    const float* __restrict__ Whh, const float* __restrict__ bih,
                    const float* __restrict__ bhh) {
    int tid = threadIdx.x, jj = blockIdx.x;
    int u0 = jj * 4, cur = t & 1, nx = (t + 1) & 1;
    float* As = scr;          // [32][66]
    float* Ws = scr + 2112;   // [32][16]
    int mt = tid >> 3, nt = tid & 7;
    int am0 = tid >> 3, ak = (tid & 7) * 4, am1 = am0 + 32;
    int wc = tid >> 3, wk = (tid & 7) * 4;
    int wrow = (wc >> 2) * 512 + u0 + (wc & 3);
    ull acc0 = 0ull, acc1 = 0ull;
    float4 va0, va1, vw = make_float4(0.f, 0.f, 0.f, 0.f);

#define LDA_CHUNK(kt_)                                                                        \
    {                                                                                         \
        va0 = ((kt_) < 512) ? __ldcg((const float4*)&g_ci[am0][(kt_) + ak])                   \
                            : __ldcg((const float4*)&g_h[cur][am0][(kt_) - 512 + ak]);        \
        va1 = ((kt_) < 512) ? __ldcg((const float4*)&g_ci[am1][(kt_) + ak])                   \
                            : __ldcg((const float4*)&g_h[cur][am1][(kt_) - 512 + ak]);        \
        if (tid < 128) {                                                                      \
            const float* ws_ = ((kt_) < 512)                                                  \
                                   ? Wih + (size_t)wrow * 512 + (kt_) + wk                    \
                                   : Whh + (size_t)wrow * 512 + ((kt_) - 512) + wk;           \
            vw = *(const float4*)ws_;                                                         \
        }                                                                                     \
    }

    LDA_CHUNK(0)
    for (int kt = 0; kt < 1024; kt += 32) {
        __syncthreads();
        As[(ak + 0) * 66 + am0] = va0.x; As[(ak + 1) * 66 + am0] = va0.y;
        As[(ak + 2) * 66 + am0] = va0.z; As[(ak + 3) * 66 + am0] = va0.w;
        As[(ak + 0) * 66 + am1] = va1.x; As[(ak + 1) * 66 + am1] = va1.y;
        As[(ak + 2) * 66 + am1] = va1.z; As[(ak + 3) * 66 + am1] = va1.w;
        if (tid < 128) {
            Ws[(wk + 0) * 16 + wc] = vw.x; Ws[(wk + 1) * 16 + wc] = vw.y;
            Ws[(wk + 2) * 16 + wc] = vw.z; Ws[(wk + 3) * 16 + wc] = vw.w;
        }
        if (kt + 32 < 1024) LDA_CHUNK(kt + 32)
        __syncthreads();
#pragma unroll
        for (int k = 0; k < 32; ++k) {
            ull a = *(const ull*)&As[k * 66 + mt * 2];
            float2 w = *(const float2*)&Ws[k * 16 + nt * 2];
            ffma2(acc0, a, dup2(w.x));
            ffma2(acc1, a, dup2(w.y));
        }
    }
#undef LDA_CHUNK
    __syncthreads();
    float* Cs = scr;          // [16][66]
    float* Ps = scr + 2700;   // 256
    {
        float2 r0 = unpk(acc0), r1 = unpk(acc1);
        Cs[(2 * nt) * 66 + 2 * mt] = r0.x; Cs[(2 * nt) * 66 + 2 * mt + 1] = r0.y;
        Cs[(2 * nt + 1) * 66 + 2 * mt] = r1.x; Cs[(2 * nt + 1) * 66 + 2 * mt + 1] = r1.y;
    }
    __syncthreads();
    int m = tid & 63, u = tid >> 6;
    int U = u0 + u;
    float gi = Cs[(u) * 66 + m]      + bih[U]        + bhh[U];
    float gf = Cs[(4 + u) * 66 + m]  + bih[512 + U]  + bhh[512 + U];
    float gg = Cs[(8 + u) * 66 + m]  + bih[1024 + U] + bhh[1024 + U];
    float go = Cs[(12 + u) * 66 + m] + bih[1536 + U] + bhh[1536 + U];
    float cc = sigf(gf) * g_c[m][U] + sigf(gi) * tanhf(gg);
    float hh = sigf(go) * tanhf(cc);
    g_c[m][U] = cc;                 // block-private across steps
    __stcg(&g_h[nx][m][U], hh);     // cross-block
    Ps[u * 64 + m] = hh;
    __syncthreads();
    if (tid < 64) {
        float h0 = Ps[tid], h1 = Ps[64 + tid], h2 = Ps[128 + tid], h3 = Ps[192 + tid];
        __stcg(&g_lnpart[jj][tid][0], h0 + h1 + h2 + h3);
        __stcg(&g_lnpart[jj][tid][1], h0 * h0 + h1 * h1 + h2 * h2 + h3 * h3);
    }
}

// phase B: heads GEMM, 4 cols per block (128 blocks), LN(h) inline
__device__ void doHeads(int q, int nx, float* scr,
                        const float* __restrict__ lnhg, const float* __restrict__ lnhb,
                        const float* __restrict__ Wrk, const float* __restrict__ Wwk,
                        const float* __restrict__ Wws, const float* __restrict__ Wer,
                        const float* __restrict__ Wad) {
    int tid = threadIdx.x;
    float* As = scr;           // [32][66]
    float* Ws = scr + 2112;    // [32][4]
    float* smean = scr + 2304; // 64
    float* srstd = scr + 2368; // 64
    if (tid < 64) {
        float s = 0.f, s2 = 0.f;
#pragma unroll 8
        for (int j = 0; j < 128; ++j) {
            float2 lp = __ldcg((const float2*)&g_lnpart[j][tid][0]);
            s += lp.x; s2 += lp.y;
        }
        float m = s * (1.f / 512);
        smean[tid] = m;
        srstd[tid] = rsqrtf(s2 * (1.f / 512) - m * m + EPS);
    }
    __syncthreads();
    int m = tid >> 2, c = tid & 3;
    int ar0 = tid >> 3, ar1 = ar0 + 32, ak = (tid & 7) * 4;
    const float* wp = headrow(q * 4 + (tid >> 3), Wrk, Wwk, Wws, Wer, Wad);  // tid<32
    float acc = 0.f;
    float4 hv0, hv1, gv0, bv0, vwh = make_float4(0.f, 0.f, 0.f, 0.f);
    hv0 = __ldcg((const float4*)&g_h[nx][ar0][ak]);
    hv1 = __ldcg((const float4*)&g_h[nx][ar1][ak]);
    gv0 = *(const float4*)&lnhg[ak];
    bv0 = *(const float4*)&lnhb[ak];
    if (tid < 32 && wp) vwh = *(const float4*)(wp + ((tid & 7) * 4));
    for (int kt = 0; kt < 512; kt += 32) {
        __syncthreads();
        {
            float mm = smean[ar0], rs = srstd[ar0];
            As[(ak + 0) * 66 + ar0] = (hv0.x - mm) * rs * gv0.x + bv0.x;
            As[(ak + 1) * 66 + ar0] = (hv0.y - mm) * rs * gv0.y + bv0.y;
            As[(ak + 2) * 66 + ar0] = (hv0.z - mm) * rs * gv0.z + bv0.z;
            As[(ak + 3) * 66 + ar0] = (hv0.w - mm) * rs * gv0.w + bv0.w;
            mm = smean[ar1]; rs = srstd[ar1];
            As[(ak + 0) * 66 + ar1] = (hv1.x - mm) * rs * gv0.x + bv0.x;
            As[(ak + 1) * 66 + ar1] = (hv1.y - mm) * rs * gv0.y + bv0.y;
            As[(ak + 2) * 66 + ar1] = (hv1.z - mm) * rs * gv0.z + bv0.z;
            As[(ak + 3) * 66 + ar1] = (hv1.w - mm) * rs * gv0.w + bv0.w;
        }
        if (tid < 32) {
            int c2 = tid >> 3, kq = (tid & 7) * 4;
            Ws[(kq + 0) * 4 + c2] = vwh.x; Ws[(kq + 1) * 4 + c2] = vwh.y;
            Ws[(kq + 2) * 4 + c2] = vwh.z; Ws[(kq + 3) * 4 + c2] = vwh.w;
        }
        if (kt + 32 < 512) {
            hv0 = __ldcg((const float4*)&g_h[nx][ar0][kt + 32 + ak]);
            hv1 = __ldcg((const float4*)&g_h[nx][ar1][kt + 32 + ak]);
            gv0 = *(const float4*)&lnhg[kt + 32 + ak];
            bv0 = *(const float4*)&lnhb[kt + 32 + ak];
            if (tid < 32 && wp) vwh = *(const float4*)(wp + kt + 32 + ((tid & 7) * 4));
        }
        __syncthreads();
#pragma unroll
        for (int k = 0; k < 32; ++k) acc += As[k * 66 + m] * Ws[k * 4 + c];
    }
    __stcg(&g_head[m][q * 4 + c], acc);
}

// phase C (blocks 64..127): proj, 16 cols per block, K=768
__device__ void doProj(int p, int trow, float* scr, const float* __restrict__ Aouts,
                       const float* __restrict__ Wproj, const float* __restrict__ bproj,
                       float* __restrict__ out) {
    int tid = threadIdx.x;
    float* As = scr;          // [32][68]
    float* Ws = scr + 2176;   // [32][20]
    int r0 = (tid >> 3) * 2, c0 = (tid & 7) * 2;
    int ar0 = tid >> 3, ar1 = ar0 + 32, ak = (tid & 7) * 4;
    int wc = tid >> 3, wk = (tid & 7) * 4;
    float a00 = 0.f, a01 = 0.f, a10 = 0.f, a11 = 0.f;
    float4 va0, va1, vw = make_float4(0.f, 0.f, 0.f, 0.f);
    va0 = __ldcg((const float4*)&Aouts[ar0 * 768 + ak]);
    va1 = __ldcg((const float4*)&Aouts[ar1 * 768 + ak]);
    if (tid < 128) vw = *(const float4*)&Wproj[(size_t)(16 * p + wc) * 768 + wk];
    for (int kt = 0; kt < 768; kt += 32) {
        __syncthreads();
        As[(ak + 0) * 68 + ar0] = va0.x; As[(ak + 1) * 68 + ar0] = va0.y;
        As[(ak + 2) * 68 + ar0] = va0.z; As[(ak + 3) * 68 + ar0] = va0.w;
        As[(ak + 0) * 68 + ar1] = va1.x; As[(ak + 1) * 68 + ar1] = va1.y;
        As[(ak + 2) * 68 + ar1] = va1.z; As[(ak + 3) * 68 + ar1] = va1.w;
        if (tid < 128) {
            Ws[(wk + 0) * 20 + wc] = vw.x; Ws[(wk + 1) * 20 + wc] = vw.y;
            Ws[(wk + 2) * 20 + wc] = vw.z; Ws[(wk + 3) * 20 + wc] = vw.w;
        }
        if (kt + 32 < 768) {
            va0 = __ldcg((const float4*)&Aouts[ar0 * 768 + kt + 32 + ak]);
            va1 = __ldcg((const float4*)&Aouts[ar1 * 768 + kt + 32 + ak]);
            if (tid < 128)
                vw = *(const float4*)&Wproj[(size_t)(16 * p + wc) * 768 + kt + 32 + wk];
        }
        __syncthreads();
#pragma unroll
        for (int k = 0; k < 32; ++k) {
            float2 a = *(const float2*)&As[k * 68 + r0];
            float2 w = *(const float2*)&Ws[k * 20 + c0];
            a00 += a.x * w.x; a01 += a.x * w.y; a10 += a.y * w.x; a11 += a.y * w.y;
        }
    }
    int col = 16 * p + c0;
    float b0 = bproj[col], b1 = bproj[col + 1];
    out[((size_t)(r0 + 0) * cL + trow) * cO + col]     = a00 + b0;
    out[((size_t)(r0 + 0) * cL + trow) * cO + col + 1] = a01 + b1;
    out[((size_t)(r0 + 1) * cL + trow) * cO + col]     = a10 + b0;
    out[((size_t)(r0 + 1) * cL + trow) * cO + col + 1] = a11 + b1;
}

// phase C (blocks 0..63): memory write/read + outln + next ci
__device__ void doMem(int t, int b, float* s_mem, float* scr, const float* __restrict__ x,
                      const float* __restrict__ brk, const float* __restrict__ bwk,
                      const float* __restrict__ bws, const float* __restrict__ ber,
                      const float* __restrict__ bad,
                      const float* __restrict__ lnhg, const float* __restrict__ lnhb,
                      const float* __restrict__ lnrkg, const float* __restrict__ lnrkb,
                      const float* __restrict__ lnwkg, const float* __restrict__ lnwkb,
                      const float* __restrict__ lnmg, const float* __restrict__ lnmb,
                      const float* __restrict__ lnog, const float* __restrict__ lnob,
                      const float* __restrict__ lning, const float* __restrict__ lninb) {
    float* s_hn = scr;           // 512
    float* s_rk = scr + 512;     // 256
    float* s_wk = scr + 768;     // 64
    float* s_er = scr + 832;     // 64
    float* s_ad = scr + 896;     // 64
    float* s_wkln = scr + 960;   // 64
    float* s_rkln = scr + 1024;  // 256
    float* s_wsc = scr + 1280;   // 256
    float* s_rsc = scr + 1536;   // 1024
    float* s_rv = scr + 2560;    // 256
    float* red = scr + 2816;     // 8
    float* misc = scr + 2824;    // 4
    int tid = threadIdx.x, warp = tid >> 5, lane = tid & 31;
    int nx = (t + 1) & 1, ob = t & 1;

    if (tid < 32) {
        float s = 0.f, s2 = 0.f;
#pragma unroll
        for (int j = 0; j < 4; ++j) {
            float2 lp = __ldcg((const float2*)&g_lnpart[lane * 4 + j][b][0]);
            s += lp.x; s2 += lp.y;
        }
#pragma unroll
        for (int o = 16; o; o >>= 1) {
            s += __shfl_xor_sync(0xffffffffu, s, o);
            s2 += __shfl_xor_sync(0xffffffffu, s2, o);
        }
        if (tid == 0) {
            float m = s * (1.f / 512);
            misc[1] = m;
            misc[2] = rsqrtf(s2 * (1.f / 512) - m * m + EPS);
        }
    }
    __syncthreads();
    float hm = misc[1], hrs = misc[2];
#pragma unroll
    for (int u = 0; u < 2; ++u) {
        int k = tid + u * 256;
        s_hn[k] = (__ldcg(&g_h[nx][b][k]) - hm) * hrs * lnhg[k] + lnhb[k];
    }
    for (int j = tid; j < 449; j += 256) {
        float v = __ldcg(&g_head[b][j]);
        if (j < 256) s_rk[j] = v + brk[j];
        else if (j < 320) s_wk[j - 256] = v + bwk[j - 256];
        else if (j == 320) misc[0] = sigf(v + bws[0]);
        else if (j < 385) s_er[j - 321] = sigf(v + ber[j - 321]);
        else s_ad[j - 385] = tanhf(v + bad[j - 385]);
    }
    __syncthreads();
    if (warp == 0) {
        float x0 = s_wk[lane], x1 = s_wk[lane + 32], s = x0 + x1;
#pragma unroll
        for (int o = 16; o; o >>= 1) s += __shfl_xor_sync(0xffffffffu, s, o);
        float mean = s * (1.f / 64), d0 = x0 - mean, d1 = x1 - mean;
        float vs = d0 * d0 + d1 * d1;
#pragma unroll
        for (int o = 16; o; o >>= 1) vs += __shfl_xor_sync(0xffffffffu, vs, o);
        float rs = rsqrtf(vs * (1.f / 64) + EPS);
        s_wkln[lane] = d0 * rs * lnwkg[lane] + lnwkb[lane];
        s_wkln[lane + 32] = d1 * rs * lnwkg[lane + 32] + lnwkb[lane + 32];
    } else if (warp <= 4) {
        int r = warp - 1;
        float x0 = s_rk[r * 64 + lane], x1 = s_rk[r * 64 + lane + 32], s = x0 + x1;
#pragma unroll
        for (int o = 16; o; o >>= 1) s += __shfl_xor_sync(0xffffffffu, s, o);
        float mean = s * (1.f / 64), d0 = x0 - mean, d1 = x1 - mean;
        float vs = d0 * d0 + d1 * d1;
#pragma unroll
        for (int o = 16; o; o >>= 1) vs += __shfl_xor_sync(0xffffffffu, vs, o);
        float rs = rsqrtf(vs * (1.f / 64) + EPS);
        s_rkln[r * 64 + lane] = d0 * rs * lnrkg[lane] + lnrkb[lane];
        s_rkln[r * 64 + lane + 32] = d1 * rs * lnrkg[lane + 32] + lnrkb[lane + 32];
    }
    __syncthreads();
    float mg0 = lnmg[lane], mg1 = lnmg[lane + 32];
    float mb0 = lnmb[lane], mb1 = lnmb[lane + 32];
    float wkl0 = s_wkln[lane], wkl1 = s_wkln[lane + 32];
    for (int m = warp; m < cM; m += 8) {
        float x0 = s_mem[m * 64 + lane], x1 = s_mem[m * 64 + lane + 32], s = x0 + x1;
#pragma unroll
        for (int o = 16; o; o >>= 1) s += __shfl_xor_sync(0xffffffffu, s, o);
        float mean = s * (1.f / 64), d0 = x0 - mean, d1 = x1 - mean;
        float vs = d0 * d0 + d1 * d1;
#pragma unroll
        for (int o = 16; o; o >>= 1) vs += __shfl_xor_sync(0xffffffffu, vs, o);
        float rs = rsqrtf(vs * (1.f / 64) + EPS);
        float dot = (d0 * rs * mg0 + mb0) * wkl0 + (d1 * rs * mg1 + mb1) * wkl1;
#pragma unroll
        for (int o = 16; o; o >>= 1) dot += __shfl_xor_sync(0xffffffffu, dot, o);
        if (lane == 0) s_wsc[m] = dot;
    }
    __syncthreads();
    {
        float v = s_wsc[tid];
        float mx = brmax(v, red);
        float e = expf(v - mx);
        float su = brsum(e, red);
        s_wsc[tid] = e / su * misc[0];
    }
    __syncthreads();
    for (int i = tid; i < cM * cHD; i += 256) {
        int m = i >> 6, hh = i & 63;
        float w = s_wsc[m];
        s_mem[i] = s_mem[i] * (1.f - w * s_er[hh]) + w * s_ad[hh];
    }
    __syncthreads();
    for (int m = warp; m < cM; m += 8) {
        float x0 = s_mem[m * 64 + lane], x1 = s_mem[m * 64 + lane + 32], s = x0 + x1;
#pragma unroll
        for (int o = 16; o; o >>= 1) s += __shfl_xor_sync(0xffffffffu, s, o);
        float mean = s * (1.f / 64), d0 = x0 - mean, d1 = x1 - mean;
        float vs = d0 * d0 + d1 * d1;
#pragma unroll
        for (int o = 16; o; o >>= 1) vs += __shfl_xor_sync(0xffffffffu, vs, o);
        float rs = rsqrtf(vs * (1.f / 64) + EPS);
        float n0 = d0 * rs * mg0 + mb0, n1 = d1 * rs * mg1 + mb1;
#pragma unroll
        for (int r = 0; r < 4; ++r) {
            float a = n0 * s_rkln[r * 64 + lane] + n1 * s_rkln[r * 64 + lane + 32];
#pragma unroll
            for (int o = 16; o; o >>= 1) a += __shfl_xor_sync(0xffffffffu, a, o);
            if (lane == 0) s_rsc[r * 256 + m] = a;
        }
    }
    __syncthreads();
#pragma unroll
    for (int r = 0; r < 4; ++r) {
        float v = s_rsc[r * 256 + tid];
        float mx = brmax(v, red);
        float e = expf(v - mx);
        float su = brsum(e, red);
        s_rsc[r * 256 + tid] = e / su;
    }
    __syncthreads();
    {
        int r = tid >> 6, hh = tid & 63;
        float a0 = 0.f, a1 = 0.f, a2 = 0.f, a3 = 0.f;
#pragma unroll 4
        for (int m = 0; m < cM; m += 4) {
            a0 += s_rsc[r * 256 + m + 0] * s_mem[(m + 0) * 64 + hh];
            a1 += s_rsc[r * 256 + m + 1] * s_mem[(m + 1) * 64 + hh];
            a2 += s_rsc[r * 256 + m + 2] * s_mem[(m + 2) * 64 + hh];
            a3 += s_rsc[r * 256 + m + 3] * s_mem[(m + 3) * 64 + hh];
        }
        s_rv[tid] = (a0 + a1) + (a2 + a3);
    }
    __syncthreads();
    {
        float o0 = s_hn[tid], o1 = s_hn[tid + 256], o2 = s_rv[tid];
        float mean = brsum(o0 + o1 + o2, red) * (1.f / cTO);
        float d0 = o0 - mean, d1 = o1 - mean, d2 = o2 - mean;
        float var = brsum(d0 * d0 + d1 * d1 + d2 * d2, red) * (1.f / cTO);
        float rs = rsqrtf(var + EPS);
        __stcg(&g_outln[ob][b][tid], d0 * rs * lnog[tid] + lnob[tid]);
        __stcg(&g_outln[ob][b][tid + 256], d1 * rs * lnog[tid + 256] + lnob[tid + 256]);
        __stcg(&g_outln[ob][b][tid + 512], d2 * rs * lnog[tid + 512] + lnob[tid + 512]);
    }
    if (t + 1 < cL) {
        const float* xn = x + ((size_t)b * cL + t + 1) * cE;
        float a0 = xn[tid], a1 = s_rv[tid];
        float mean = brsum(a0 + a1, red) * (1.f / cCI);
        float d0 = a0 - mean, d1 = a1 - mean;
        float var = brsum(d0 * d0 + d1 * d1, red) * (1.f / cCI);
        float rs = rsqrtf(var + EPS);
        __stcg(&g_ci[b][tid], d0 * rs * lning[tid] + lninb[tid]);
        __stcg(&g_ci[b][tid + 256], d1 * rs * lning[tid + 256] + lninb[tid + 256]);
    }
}

__global__ void __launch_bounds__(256, 1) k_persist(
    const float* __restrict__ x, const float* __restrict__ Wih,
    const float* __restrict__ Whh, const float* __restrict__ bih,
    const float* __restrict__ bhh, const float* __restrict__ lning,
    const float* __restrict__ lninb, const float* __restrict__ lnhg,
    const float* __restrict__ lnhb, const float* __restrict__ Wrk,
    const float* __restrict__ brk, const float* __restrict__ Wwk,
    const float* __restrict__ bwk, const float* __restrict__ Wws,
    const float* __restrict__ bws, const float* __restrict__ Wer,
    const float* __restrict__ ber, const float* __restrict__ Wad,
    const float* __restrict__ bad, const float* __restrict__ lnrkg,
    const float* __restrict__ lnrkb, const float* __restrict__ lnwkg,
    const float* __restrict__ lnwkb, const float* __restrict__ lnmg,
    const float* __restrict__ lnmb, const float* __restrict__ lnog,
    const float* __restrict__ lnob, const float* __restrict__ Wproj,
    const float* __restrict__ bproj, float* __restrict__ out,
    float* __restrict__ memg, float* __restrict__ hout, float* __restrict__ cout) {
    extern __shared__ float sm[];
    float* s_mem = sm;          // 16384 (persistent memory, blocks 0..63)
    float* scr = sm + 16384;    // 4096 scratch
    int bx = blockIdx.x, tid = threadIdx.x;

    if (bx < 64) {
        for (int i = tid; i < cM * cHD; i += 256) s_mem[i] = 0.f;
        int b = bx;
#pragma unroll
        for (int u = 0; u < 2; ++u) {
            int k = tid + u * 256;
            g_c[b][k] = 0.f;
            __stcg(&g_h[0][b][k], 0.f);
        }
        float* red = scr;
        float a0 = x[(size_t)b * cL * cE + tid];
        float mean = brsum(a0, red) * (1.f / cCI);
        float d0 = a0 - mean, d1 = -mean;
        float var = brsum(d0 * d0 + d1 * d1, red) * (1.f / cCI);
        float rs = rsqrtf(var + EPS);
        __stcg(&g_ci[b][tid], d0 * rs * lning[tid] + lninb[tid]);
        __stcg(&g_ci[b][tid + 256], d1 * rs * lning[tid + 256] + lninb[tid + 256]);
    }
    gsync();

    for (int t = 0; t < cL; ++t) {
        doA(t, scr, Wih, Whh, bih, bhh);
        gsync();
        doHeads(bx, (t + 1) & 1, scr, lnhg, lnhb, Wrk, Wwk, Wws, Wer, Wad);
        gsync();
        if (bx < 64) {
            doMem(t, bx, s_mem, scr, x, brk, bwk, bws, ber, bad, lnhg, lnhb,
                  lnrkg, lnrkb, lnwkg, lnwkb, lnmg, lnmb, lnog, lnob, lning, lninb);
        } else if (t > 0) {
            doProj(bx - 64, t - 1, scr, &g_outln[(t - 1) & 1][0][0], Wproj, bproj, out);
        }
        gsync();
    }
    if (bx >= 64) {
        doProj(bx - 64, cL - 1, scr, &g_outln[(cL - 1) & 1][0][0], Wproj, bproj, out);
    } else {
        int b = bx;
        for (int i = tid; i < cM * cHD; i += 256) memg[(size_t)b * cM * cHD + i] = s_mem[i];
#pragma unroll
        for (int u = 0; u < 2; ++u) {
            int k = tid + u * 256;
            hout[b * cH + k] = __ldcg(&g_h[0][b][k]);
            cout[b * cH + k] = __ldcg(&g_c[b][k]);
        }
    }
}

extern "C" void kernel_launch(void* const* d_in, const int* in_sizes, int n_in,
                              void* d_out, int out_size) {
    const float** p = (const float**)d_in;
    float* out = (float*)d_out;
    float* memg = out + (size_t)cB * cL * cO;
    float* hout = memg + (size_t)cB * cM * cHD;
    float* cout = hout + (size_t)cB * cH;
    const int smem = (16384 + 4096) * 4;
    cudaFuncSetAttribute(k_persist, cudaFuncAttributeMaxDynamicSharedMemorySize, smem);
    k_persist<<<NBLK, 256, smem>>>(p[0], p[1], p[2], p[3], p[4], p[5], p[6], p[7], p[8],
                                   p[9], p[10], p[11], p[12], p[13], p[14], p[15], p[16],
                                   p[17], p[18], p[19], p[20], p[21], p[22], p[23], p[24],
                                   p[25], p[26], p[27], p[28], out, memg, hout, cout);
}

// round 15
// speedup vs baseline: 1.4702x; 1.2361x over previous
#include <cuda_runtime.h>
#include <math.h>

#define cB 64
#define cL 256
#define cE 256
#define cH 512
#define cM 256
#define cHD 64
#define cO 1024
#define cCI 512
#define cTO 768
#define EPS 1e-5f
#define NBLK 128
#define SCRF 6656

typedef unsigned long long ull;

__device__ float g_h[2][cB][cH];
__device__ float g_c[cB][cH];
__device__ float g_ci[cB][cCI];
__device__ float g_outln[2][cB][cTO];
__device__ float g_head[cB][512];
__device__ float g_lnpart[128][cB][2];
__device__ unsigned g_cnt = 0;
__device__ unsigned g_gen = 0;

__device__ __forceinline__ float sigf(float x) { return 1.0f / (1.0f + expf(-x)); }

__device__ __forceinline__ ull dup2(float w) {
    ull r;
    asm("mov.b64 %0, {%1, %1};" : "=l"(r) : "f"(w));
    return r;
}
__device__ __forceinline__ void ffma2(ull& acc, ull a, ull b) {
    asm("fma.rn.f32x2 %0, %1, %2, %0;" : "+l"(acc) : "l"(a), "l"(b));
}
__device__ __forceinline__ float2 unpk(ull v) {
    float2 r;
    asm("mov.b64 {%0, %1}, %2;" : "=f"(r.x), "=f"(r.y) : "l"(v));
    return r;
}

// CG-style grid barrier (no CCTL/L1 flush). Cross-block data via __ldcg/__stcg.
__device__ __forceinline__ void gsync() {
    __syncthreads();
    if (threadIdx.x == 0) {
        unsigned gen;
        asm volatile("ld.relaxed.gpu.global.u32 %0, [%1];" : "=r"(gen) : "l"(&g_gen));
        unsigned prev;
        asm volatile("atom.acq_rel.gpu.global.add.u32 %0, [%1], %2;"
                     : "=r"(prev) : "l"(&g_cnt), "r"(1u) : "memory");
        if (prev == NBLK - 1) {
            asm volatile("st.relaxed.gpu.global.u32 [%0], %1;" :: "l"(&g_cnt), "r"(0u) : "memory");
            asm volatile("st.release.gpu.global.u32 [%0], %1;" :: "l"(&g_gen), "r"(gen + 1u) : "memory");
        } else {
            unsigned cur;
            do {
                asm volatile("ld.acquire.gpu.global.u32 %0, [%1];" : "=r"(cur) : "l"(&g_gen) : "memory");
            } while (cur == gen);
        }
    }
    __syncthreads();
}

// block reductions for 512 threads (16 warps)
__device__ __forceinline__ float brsum(float v, float* red) {
    int tid = threadIdx.x;
#pragma unroll
    for (int o = 16; o; o >>= 1) v += __shfl_xor_sync(0xffffffffu, v, o);
    if ((tid & 31) == 0) red[tid >> 5] = v;
    __syncthreads();
    if (tid == 0) { float s = 0.f; for (int i = 0; i < 16; ++i) s += red[i]; red[0] = s; }
    __syncthreads();
    float r = red[0];
    __syncthreads();
    return r;
}
__device__ __forceinline__ float brmax(float v, float* red) {
    int tid = threadIdx.x;
#pragma unroll
    for (int o = 16; o; o >>= 1) v = fmaxf(v, __shfl_xor_sync(0xffffffffu, v, o));
    if ((tid & 31) == 0) red[tid >> 5] = v;
    __syncthreads();
    if (tid == 0) { float s = red[0]; for (int i = 1; i < 16; ++i) s = fmaxf(s, red[i]); red[0] = s; }
    __syncthreads();
    float r = red[0];
    __syncthreads();
    return r;
}

__device__ __forceinline__ const float* headrow(int g, const float* Wrk, const float* Wwk,
                                                const float* Wws, const float* Wer,
                                                const float* Wad) {
    if (g < 256) return Wrk + (size_t)g * 512;
    if (g < 320) return Wwk + (size_t)(g - 256) * 512;
    if (g == 320) return Wws;
    if (g < 385) return Wer + (size_t)(g - 321) * 512;
    if (g < 449) return Wad + (size_t)(g - 385) * 512;
    return nullptr;
}

// phase A: gates GEMM [64x16, K=1024] split-K across half-blocks + fused LSTM
__device__ void doA(int t, float* scr, const float* __restrict__ Wih,
                    const float* __restrict__ Whh, const float* __restrict__ bih,
                    const float* __restrict__ bhh) {
    int tid = threadIdx.x, jj = blockIdx.x;
    int u0 = jj * 4, cur = t & 1, nx = (t + 1) & 1;
    int half = tid >> 8, ltid = tid & 255;
    float* As = scr + half * 2112;         // [32][66] per half
    float* Ws = scr + 4224 + half * 512;   // [32][16] per half
    const float* Ab = half ? &g_h[cur][0][0] : &g_ci[0][0];
    const float* Wb = half ? Whh : Wih;
    int mt = ltid >> 3, nt = ltid & 7;
    int am0 = ltid >> 3, ak = (ltid & 7) * 4, am1 = am0 + 32;
    int wc = ltid >> 3, wk = (ltid & 7) * 4;
    int wrow = (wc >> 2) * 512 + u0 + (wc & 3);
    ull acc0 = 0ull, acc1 = 0ull;
    float4 va0, va1, vw = make_float4(0.f, 0.f, 0.f, 0.f);
    va0 = __ldcg((const float4*)(Ab + am0 * 512 + ak));
    va1 = __ldcg((const float4*)(Ab + am1 * 512 + ak));
    if (ltid < 128) vw = *(const float4*)(Wb + (size_t)wrow * 512 + wk);
    for (int kt = 0; kt < 512; kt += 32) {
        __syncthreads();
        As[(ak + 0) * 66 + am0] = va0.x; As[(ak + 1) * 66 + am0] = va0.y;
        As[(ak + 2) * 66 + am0] = va0.z; As[(ak + 3) * 66 + am0] = va0.w;
        As[(ak + 0) * 66 + am1] = va1.x; As[(ak + 1) * 66 + am1] = va1.y;
        As[(ak + 2) * 66 + am1] = va1.z; As[(ak + 3) * 66 + am1] = va1.w;
        if (ltid < 128) {
            Ws[(wk + 0) * 16 + wc] = vw.x; Ws[(wk + 1) * 16 + wc] = vw.y;
            Ws[(wk + 2) * 16 + wc] = vw.z; Ws[(wk + 3) * 16 + wc] = vw.w;
        }
        if (kt + 32 < 512) {
            va0 = __ldcg((const float4*)(Ab + am0 * 512 + kt + 32 + ak));
            va1 = __ldcg((const float4*)(Ab + am1 * 512 + kt + 32 + ak));
            if (ltid < 128) vw = *(const float4*)(Wb + (size_t)wrow * 512 + kt + 32 + wk);
        }
        __syncthreads();
#pragma unroll
        for (int k = 0; k < 32; ++k) {
            ull a = *(const ull*)&As[k * 66 + mt * 2];
            float2 w = *(const float2*)&Ws[k * 16 + nt * 2];
            ffma2(acc0, a, dup2(w.x));
            ffma2(acc1, a, dup2(w.y));
        }
    }
    __syncthreads();
    float* P1 = scr;          // 1024 (half1 partials)
    float* Cs = scr + 1024;   // [16][66]
    float* Ps = scr + 2112;   // 256
    if (half == 1) {
        float2 r0 = unpk(acc0), r1 = unpk(acc1);
        *(float4*)&P1[ltid * 4] = make_float4(r0.x, r0.y, r1.x, r1.y);
    }
    __syncthreads();
    if (half == 0) {
        float4 o = *(const float4*)&P1[ltid * 4];
        float2 r0 = unpk(acc0), r1 = unpk(acc1);
        Cs[(2 * nt) * 66 + 2 * mt] = r0.x + o.x;
        Cs[(2 * nt) * 66 + 2 * mt + 1] = r0.y + o.y;
        Cs[(2 * nt + 1) * 66 + 2 * mt] = r1.x + o.z;
        Cs[(2 * nt + 1) * 66 + 2 * mt + 1] = r1.y + o.w;
    }
    __syncthreads();
    if (tid < 256) {
        int m = tid & 63, u = tid >> 6;
        int U = u0 + u;
        float gi = Cs[(u) * 66 + m]      + bih[U]        + bhh[U];
        float gf = Cs[(4 + u) * 66 + m]  + bih[512 + U]  + bhh[512 + U];
        float gg = Cs[(8 + u) * 66 + m]  + bih[1024 + U] + bhh[1024 + U];
        float go = Cs[(12 + u) * 66 + m] + bih[1536 + U] + bhh[1536 + U];
        float cc = sigf(gf) * g_c[m][U] + sigf(gi) * tanhf(gg);
        float hh = sigf(go) * tanhf(cc);
        g_c[m][U] = cc;
        __stcg(&g_h[nx][m][U], hh);
        Ps[u * 64 + m] = hh;
    }
    __syncthreads();
    if (tid < 64) {
        float h0 = Ps[tid], h1 = Ps[64 + tid], h2 = Ps[128 + tid], h3 = Ps[192 + tid];
        __stcg(&g_lnpart[jj][tid][0], h0 + h1 + h2 + h3);
        __stcg(&g_lnpart[jj][tid][1], h0 * h0 + h1 * h1 + h2 * h2 + h3 * h3);
    }
}

// phase B: heads GEMM, 4 cols/block, K split 2x256, LN(h) inline
__device__ void doHeads(int q, int nx, float* scr,
                        const float* __restrict__ lnhg, const float* __restrict__ lnhb,
                        const float* __restrict__ Wrk, const float* __restrict__ Wwk,
                        const float* __restrict__ Wws, const float* __restrict__ Wer,
                        const float* __restrict__ Wad) {
    int tid = threadIdx.x;
    int half = tid >> 8, ltid = tid & 255;
    float* As = scr + half * 2112;         // [32][66]
    float* Ws = scr + 4224 + half * 128;   // [32][4]
    float* smean = scr + 4480;             // 64
    float* srstd = scr + 4544;             // 64
    float* hacc = scr + 4608;              // 512
    if (tid < 64) {
        float s = 0.f, s2 = 0.f;
#pragma unroll 8
        for (int j = 0; j < 128; ++j) {
            float2 lp = __ldcg((const float2*)&g_lnpart[j][tid][0]);
            s += lp.x; s2 += lp.y;
        }
        float m = s * (1.f / 512);
        smean[tid] = m;
        srstd[tid] = rsqrtf(s2 * (1.f / 512) - m * m + EPS);
    }
    __syncthreads();
    int m = ltid >> 2, c = ltid & 3;
    int ar0 = ltid >> 3, ar1 = ar0 + 32, ak = (ltid & 7) * 4;
    int kb = half * 256;
    const float* wp = headrow(q * 4 + (ltid >> 3), Wrk, Wwk, Wws, Wer, Wad);  // ltid<32
    float acc = 0.f;
    float4 hv0, hv1, gv0, bv0, vwh = make_float4(0.f, 0.f, 0.f, 0.f);
    hv0 = __ldcg((const float4*)&g_h[nx][ar0][kb + ak]);
    hv1 = __ldcg((const float4*)&g_h[nx][ar1][kb + ak]);
    gv0 = *(const float4*)&lnhg[kb + ak];
    bv0 = *(const float4*)&lnhb[kb + ak];
    if (ltid < 32 && wp) vwh = *(const float4*)(wp + kb + ((ltid & 7) * 4));
    for (int kt = 0; kt < 256; kt += 32) {
        __syncthreads();
        {
            float mm = smean[ar0], rs = srstd[ar0];
            As[(ak + 0) * 66 + ar0] = (hv0.x - mm) * rs * gv0.x + bv0.x;
            As[(ak + 1) * 66 + ar0] = (hv0.y - mm) * rs * gv0.y + bv0.y;
            As[(ak + 2) * 66 + ar0] = (hv0.z - mm) * rs * gv0.z + bv0.z;
            As[(ak + 3) * 66 + ar0] = (hv0.w - mm) * rs * gv0.w + bv0.w;
            mm = smean[ar1]; rs = srstd[ar1];
            As[(ak + 0) * 66 + ar1] = (hv1.x - mm) * rs * gv0.x + bv0.x;
            As[(ak + 1) * 66 + ar1] = (hv1.y - mm) * rs * gv0.y + bv0.y;
            As[(ak + 2) * 66 + ar1] = (hv1.z - mm) * rs * gv0.z + bv0.z;
            As[(ak + 3) * 66 + ar1] = (hv1.w - mm) * rs * gv0.w + bv0.w;
        }
        if (ltid < 32) {
            int c2 = ltid >> 3, kq = (ltid & 7) * 4;
            Ws[(kq + 0) * 4 + c2] = vwh.x; Ws[(kq + 1) * 4 + c2] = vwh.y;
            Ws[(kq + 2) * 4 + c2] = vwh.z; Ws[(kq + 3) * 4 + c2] = vwh.w;
        }
        if (kt + 32 < 256) {
            hv0 = __ldcg((const float4*)&g_h[nx][ar0][kb + kt + 32 + ak]);
            hv1 = __ldcg((const float4*)&g_h[nx][ar1][kb + kt + 32 + ak]);
            gv0 = *(const float4*)&lnhg[kb + kt + 32 + ak];
            bv0 = *(const float4*)&lnhb[kb + kt + 32 + ak];
            if (ltid < 32 && wp) vwh = *(const float4*)(wp + kb + kt + 32 + ((ltid & 7) * 4));
        }
        __syncthreads();
#pragma unroll
        for (int k = 0; k < 32; ++k) acc += As[k * 66 + m] * Ws[k * 4 + c];
    }
    hacc[tid] = acc;
    __syncthreads();
    if (tid < 256) __stcg(&g_head[m][q * 4 + c], hacc[tid] + hacc[tid + 256]);
}

// phase C (blocks 64..127): proj, 16 cols/block, K split 2x384
__device__ void doProj(int p, int trow, float* scr, const float* __restrict__ Aouts,
                       const float* __restrict__ Wproj, const float* __restrict__ bproj,
                       float* __restrict__ out) {
    int tid = threadIdx.x;
    int half = tid >> 8, ltid = tid & 255;
    float* As = scr + half * 2176;         // [32][68]
    float* Ws = scr + 4352 + half * 640;   // [32][20]
    float* pacc = scr + 5632;              // 1024
    int r0 = (ltid >> 3) * 2, c0 = (ltid & 7) * 2;
    int ar0 = ltid >> 3, ar1 = ar0 + 32, ak = (ltid & 7) * 4;
    int wc = ltid >> 3, wk = (ltid & 7) * 4;
    int kb = half * 384;
    float a00 = 0.f, a01 = 0.f, a10 = 0.f, a11 = 0.f;
    float4 va0, va1, vw = make_float4(0.f, 0.f, 0.f, 0.f);
    va0 = __ldcg((const float4*)&Aouts[ar0 * 768 + kb + ak]);
    va1 = __ldcg((const float4*)&Aouts[ar1 * 768 + kb + ak]);
    if (ltid < 128) vw = *(const float4*)&Wproj[(size_t)(16 * p + wc) * 768 + kb + wk];
    for (int kt = 0; kt < 384; kt += 32) {
        __syncthreads();
        As[(ak + 0) * 68 + ar0] = va0.x; As[(ak + 1) * 68 + ar0] = va0.y;
        As[(ak + 2) * 68 + ar0] = va0.z; As[(ak + 3) * 68 + ar0] = va0.w;
        As[(ak + 0) * 68 + ar1] = va1.x; As[(ak + 1) * 68 + ar1] = va1.y;
        As[(ak + 2) * 68 + ar1] = va1.z; As[(ak + 3) * 68 + ar1] = va1.w;
        if (ltid < 128) {
            Ws[(wk + 0) * 20 + wc] = vw.x; Ws[(wk + 1) * 20 + wc] = vw.y;
            Ws[(wk + 2) * 20 + wc] = vw.z; Ws[(wk + 3) * 20 + wc] = vw.w;
        }
        if (kt + 32 < 384) {
            va0 = __ldcg((const float4*)&Aouts[ar0 * 768 + kb + kt + 32 + ak]);
            va1 = __ldcg((const float4*)&Aouts[ar1 * 768 + kb + kt + 32 + ak]);
            if (ltid < 128)
                vw = *(const float4*)&Wproj[(size_t)(16 * p + wc) * 768 + kb + kt + 32 + wk];
        }
        __syncthreads();
#pragma unroll
        for (int k = 0; k < 32; ++k) {
            float2 a = *(const float2*)&As[k * 68 + r0];
            float2 w = *(const float2*)&Ws[k * 20 + c0];
            a00 += a.x * w.x; a01 += a.x * w.y; a10 += a.y * w.x; a11 += a.y * w.y;
        }
    }
    __syncthreads();
    if (half == 1) *(float4*)&pacc[ltid * 4] = make_float4(a00, a01, a10, a11);
    __syncthreads();
    if (half == 0) {
        float4 o = *(const float4*)&pacc[ltid * 4];
        int col = 16 * p + c0;
        float b0 = bproj[col], b1 = bproj[col + 1];
        out[((size_t)(r0 + 0) * cL + trow) * cO + col]     = a00 + o.x + b0;
        out[((size_t)(r0 + 0) * cL + trow) * cO + col + 1] = a01 + o.y + b1;
        out[((size_t)(r0 + 1) * cL + trow) * cO + col]     = a10 + o.z + b0;
        out[((size_t)(r0 + 1) * cL + trow) * cO + col + 1] = a11 + o.w + b1;
    }
}

// phase C (blocks 0..63): memory write/read + outln + next ci (512 threads)
__device__ void doMem(int t, int b, float* s_mem, float* scr, const float* __restrict__ x,
                      const float* __restrict__ brk, const float* __restrict__ bwk,
                      const float* __restrict__ bws, const float* __restrict__ ber,
                      const float* __restrict__ bad,
                      const float* __restrict__ lnhg, const float* __restrict__ lnhb,
                      const float* __restrict__ lnrkg, const float* __restrict__ lnrkb,
                      const float* __restrict__ lnwkg, const float* __restrict__ lnwkb,
                      const float* __restrict__ lnmg, const float* __restrict__ lnmb,
                      const float* __restrict__ lnog, const float* __restrict__ lnob,
                      const float* __restrict__ lning, const float* __restrict__ lninb) {
    float* s_hn = scr;           // 512
    float* s_rk = scr + 512;     // 256
    float* s_wk = scr + 768;     // 64
    float* s_er = scr + 832;     // 64
    float* s_ad = scr + 896;     // 64
    float* s_wkln = scr + 960;   // 64
    float* s_rkln = scr + 1024;  // 256
    float* s_wsc = scr + 1280;   // 256
    float* s_rsc = scr + 1536;   // 1024
    float* s_rv = scr + 2560;    // 256
    float* s_rvp = scr + 2816;   // 512
    float* red = scr + 3328;     // 16
    float* misc = scr + 3344;    // 4
    int tid = threadIdx.x, warp = tid >> 5, lane = tid & 31;
    int nx = (t + 1) & 1, ob = t & 1;

    if (tid < 32) {
        float s = 0.f, s2 = 0.f;
#pragma unroll
        for (int j = 0; j < 4; ++j) {
            float2 lp = __ldcg((const float2*)&g_lnpart[lane * 4 + j][b][0]);
            s += lp.x; s2 += lp.y;
        }
#pragma unroll
        for (int o = 16; o; o >>= 1) {
            s += __shfl_xor_sync(0xffffffffu, s, o);
            s2 += __shfl_xor_sync(0xffffffffu, s2, o);
        }
        if (tid == 0) {
            float m = s * (1.f / 512);
            misc[1] = m;
            misc[2] = rsqrtf(s2 * (1.f / 512) - m * m + EPS);
        }
    }
    __syncthreads();
    float hm = misc[1], hrs = misc[2];
    s_hn[tid] = (__ldcg(&g_h[nx][b][tid]) - hm) * hrs * lnhg[tid] + lnhb[tid];
    if (tid < 449) {
        float v = __ldcg(&g_head[b][tid]);
        if (tid < 256) s_rk[tid] = v + brk[tid];
        else if (tid < 320) s_wk[tid - 256] = v + bwk[tid - 256];
        else if (tid == 320) misc[0] = sigf(v + bws[0]);
        else if (tid < 385) s_er[tid - 321] = sigf(v + ber[tid - 321]);
        else s_ad[tid - 385] = tanhf(v + bad[tid - 385]);
    }
    __syncthreads();
    if (warp == 0) {
        float x0 = s_wk[lane], x1 = s_wk[lane + 32], s = x0 + x1;
#pragma unroll
        for (int o = 16; o; o >>= 1) s += __shfl_xor_sync(0xffffffffu, s, o);
        float mean = s * (1.f / 64), d0 = x0 - mean, d1 = x1 - mean;
        float vs = d0 * d0 + d1 * d1;
#pragma unroll
        for (int o = 16; o; o >>= 1) vs += __shfl_xor_sync(0xffffffffu, vs, o);
        float rs = rsqrtf(vs * (1.f / 64) + EPS);
        s_wkln[lane] = d0 * rs * lnwkg[lane] + lnwkb[lane];
        s_wkln[lane + 32] = d1 * rs * lnwkg[lane + 32] + lnwkb[lane + 32];
    } else if (warp <= 4) {
        int r = warp - 1;
        float x0 = s_rk[r * 64 + lane], x1 = s_rk[r * 64 + lane + 32], s = x0 + x1;
#pragma unroll
        for (int o = 16; o; o >>= 1) s += __shfl_xor_sync(0xffffffffu, s, o);
        float mean = s * (1.f / 64), d0 = x0 - mean, d1 = x1 - mean;
        float vs = d0 * d0 + d1 * d1;
#pragma unroll
        for (int o = 16; o; o >>= 1) vs += __shfl_xor_sync(0xffffffffu, vs, o);
        float rs = rsqrtf(vs * (1.f / 64) + EPS);
        s_rkln[r * 64 + lane] = d0 * rs * lnrkg[lane] + lnrkb[lane];
        s_rkln[r * 64 + lane + 32] = d1 * rs * lnrkg[lane + 32] + lnrkb[lane + 32];
    }
    __syncthreads();
    float mg0 = lnmg[lane], mg1 = lnmg[lane + 32];
    float mb0 = lnmb[lane], mb1 = lnmb[lane + 32];
    float wkl0 = s_wkln[lane], wkl1 = s_wkln[lane + 32];
    for (int m = warp; m < cM; m += 16) {
        float x0 = s_mem[m * 64 + lane], x1 = s_mem[m * 64 + lane + 32], s = x0 + x1;
#pragma unroll
        for (int o = 16; o; o >>= 1) s += __shfl_xor_sync(0xffffffffu, s, o);
        float mean = s * (1.f / 64), d0 = x0 - mean, d1 = x1 - mean;
        float vs = d0 * d0 + d1 * d1;
#pragma unroll
        for (int o = 16; o; o >>= 1) vs += __shfl_xor_sync(0xffffffffu, vs, o);
        float rs = rsqrtf(vs * (1.f / 64) + EPS);
        float dot = (d0 * rs * mg0 + mb0) * wkl0 + (d1 * rs * mg1 + mb1) * wkl1;
#pragma unroll
        for (int o = 16; o; o >>= 1) dot += __shfl_xor_sync(0xffffffffu, dot, o);
        if (lane == 0) s_wsc[m] = dot;
    }
    __syncthreads();
    {
        float v = (tid < 256) ? s_wsc[tid] : -3e38f;
        float mx = brmax(v, red);
        float e = (tid < 256) ? expf(v - mx) : 0.f;
        float su = brsum(e, red);
        if (tid < 256) s_wsc[tid] = e / su * misc[0];
    }
    __syncthreads();
    for (int i = tid; i < cM * cHD; i += 512) {
        int m = i >> 6, hh = i & 63;
        float w = s_wsc[m];
        s_mem[i] = s_mem[i] * (1.f - w * s_er[hh]) + w * s_ad[hh];
    }
    __syncthreads();
    for (int m = warp; m < cM; m += 16) {
        float x0 = s_mem[m * 64 + lane], x1 = s_mem[m * 64 + lane + 32], s = x0 + x1;
#pragma unroll
        for (int o = 16; o; o >>= 1) s += __shfl_xor_sync(0xffffffffu, s, o);
        float mean = s * (1.f / 64), d0 = x0 - mean, d1 = x1 - mean;
        float vs = d0 * d0 + d1 * d1;
#pragma unroll
        for (int o = 16; o; o >>= 1) vs += __shfl_xor_sync(0xffffffffu, vs, o);
        float rs = rsqrtf(vs * (1.f / 64) + EPS);
        float n0 = d0 * rs * mg0 + mb0, n1 = d1 * rs * mg1 + mb1;
#pragma unroll
        for (int r = 0; r < 4; ++r) {
            float a = n0 * s_rkln[r * 64 + lane] + n1 * s_rkln[r * 64 + lane + 32];
#pragma unroll
            for (int o = 16; o; o >>= 1) a += __shfl_xor_sync(0xffffffffu, a, o);
            if (lane == 0) s_rsc[r * 256 + m] = a;
        }
    }
    __syncthreads();
#pragma unroll
    for (int r = 0; r < 4; ++r) {
        float v = (tid < 256) ? s_rsc[r * 256 + tid] : -3e38f;
        float mx = brmax(v, red);
        float e = (tid < 256) ? expf(v - mx) : 0.f;
        float su = brsum(e, red);
        if (tid < 256) s_rsc[r * 256 + tid] = e / su;
    }
    __syncthreads();
    {
        int r = tid >> 7, rest = tid & 127, hf = rest >> 6, hh = rest & 63;
        int mb = hf * 128;
        float a0 = 0.f, a1 = 0.f, a2 = 0.f, a3 = 0.f;
#pragma unroll 4
        for (int m = 0; m < 128; m += 4) {
            a0 += s_rsc[r * 256 + mb + m + 0] * s_mem[(mb + m + 0) * 64 + hh];
            a1 += s_rsc[r * 256 + mb + m + 1] * s_mem[(mb + m + 1) * 64 + hh];
            a2 += s_rsc[r * 256 + mb + m + 2] * s_mem[(mb + m + 2) * 64 + hh];
            a3 += s_rsc[r * 256 + mb + m + 3] * s_mem[(mb + m + 3) * 64 + hh];
        }
        s_rvp[tid] = (a0 + a1) + (a2 + a3);
    }
    __syncthreads();
    if (tid < 256) {
        int r = tid >> 6, hh = tid & 63;
        s_rv[tid] = s_rvp[r * 128 + hh] + s_rvp[r * 128 + 64 + hh];
    }
    __syncthreads();
    {
        float o0 = s_hn[tid];
        float o2 = (tid < 256) ? s_rv[tid] : 0.f;
        float mean = brsum(o0 + o2, red) * (1.f / cTO);
        float d0 = o0 - mean, d2 = o2 - mean;
        float var = brsum(d0 * d0 + ((tid < 256) ? d2 * d2 : 0.f), red) * (1.f / cTO);
        float rs = rsqrtf(var + EPS);
        __stcg(&g_outln[ob][b][tid], d0 * rs * lnog[tid] + lnob[tid]);
        if (tid < 256)
            __stcg(&g_outln[ob][b][512 + tid], d2 * rs * lnog[512 + tid] + lnob[512 + tid]);
    }
    if (t + 1 < cL) {
        const float* xn = x + ((size_t)b * cL + t + 1) * cE;
        float a = (tid < 256) ? xn[tid] : s_rv[tid - 256];
        float mean = brsum(a, red) * (1.f / cCI);
        float d = a - mean;
        float var = brsum(d * d, red) * (1.f / cCI);
        float rs = rsqrtf(var + EPS);
        __stcg(&g_ci[b][tid], d * rs * lning[tid] + lninb[tid]);
    }
}

__global__ void __launch_bounds__(512, 1) k_persist(
    const float* __restrict__ x, const float* __restrict__ Wih,
    const float* __restrict__ Whh, const float* __restrict__ bih,
    const float* __restrict__ bhh, const float* __restrict__ lning,
    const float* __restrict__ lninb, const float* __restrict__ lnhg,
    const float* __restrict__ lnhb, const float* __restrict__ Wrk,
    const float* __restrict__ brk, const float* __restrict__ Wwk,
    const float* __restrict__ bwk, const float* __restrict__ Wws,
    const float* __restrict__ bws, const float* __restrict__ Wer,
    const float* __restrict__ ber, const float* __restrict__ Wad,
    const float* __restrict__ bad, const float* __restrict__ lnrkg,
    const float* __restrict__ lnrkb, const float* __restrict__ lnwkg,
    const float* __restrict__ lnwkb, const float* __restrict__ lnmg,
    const float* __restrict__ lnmb, const float* __restrict__ lnog,
    const float* __restrict__ lnob, const float* __restrict__ Wproj,
    const float* __restrict__ bproj, float* __restrict__ out,
    float* __restrict__ memg, float* __restrict__ hout, float* __restrict__ cout) {
    extern __shared__ float sm[];
    float* s_mem = sm;          // 16384 (persistent memory, blocks 0..63)
    float* scr = sm + 16384;    // SCRF scratch
    int bx = blockIdx.x, tid = threadIdx.x;

    if (bx < 64) {
        for (int i = tid; i < cM * cHD; i += 512) s_mem[i] = 0.f;
        int b = bx;
        g_c[b][tid] = 0.f;
        __stcg(&g_h[0][b][tid], 0.f);
        float* red = scr;
        float a = (tid < 256) ? x[(size_t)b * cL * cE + tid] : 0.f;
        float mean = brsum(a, red) * (1.f / cCI);
        float d = a - mean;
        float var = brsum(d * d, red) * (1.f / cCI);
        float rs = rsqrtf(var + EPS);
        __stcg(&g_ci[b][tid], d * rs * lning[tid] + lninb[tid]);
    }
    gsync();

    for (int t = 0; t < cL; ++t) {
        doA(t, scr, Wih, Whh, bih, bhh);
        gsync();
        doHeads(bx, (t + 1) & 1, scr, lnhg, lnhb, Wrk, Wwk, Wws, Wer, Wad);
        gsync();
        if (bx < 64) {
            doMem(t, bx, s_mem, scr, x, brk, bwk, bws, ber, bad, lnhg, lnhb,
                  lnrkg, lnrkb, lnwkg, lnwkb, lnmg, lnmb, lnog, lnob, lning, lninb);
        } else if (t > 0) {
            doProj(bx - 64, t - 1, scr, &g_outln[(t - 1) & 1][0][0], Wproj, bproj, out);
        }
        gsync();
    }
    if (bx >= 64) {
        doProj(bx - 64, cL - 1, scr, &g_outln[(cL - 1) & 1][0][0], Wproj, bproj, out);
    } else {
        int b = bx;
        for (int i = tid; i < cM * cHD; i += 512) memg[(size_t)b * cM * cHD + i] = s_mem[i];
        hout[b * cH + tid] = __ldcg(&g_h[0][b][tid]);
        cout[b * cH + tid] = __ldcg(&g_c[b][tid]);
    }
}

extern "C" void kernel_launch(void* const* d_in, const int* in_sizes, int n_in,
                              void* d_out, int out_size) {
    const float** p = (const float**)d_in;
    float* out = (float*)d_out;
    float* memg = out + (size_t)cB * cL * cO;
    float* hout = memg + (size_t)cB * cM * cHD;
    float* cout = hout + (size_t)cB * cH;
    const int smem = (16384 + SCRF) * 4;
    cudaFuncSetAttribute(k_persist, cudaFuncAttributeMaxDynamicSharedMemorySize, smem);
    k_persist<<<NBLK, 512, smem>>>(p[0], p[1], p[2], p[3], p[4], p[5], p[6], p[7], p[8],
                                   p[9], p[10], p[11], p[12], p[13], p[14], p[15], p[16],
                                   p[17], p[18], p[19], p[20], p[21], p[22], p[23], p[24],
                                   p[25], p[26], p[27], p[28], out, memg, hout, cout);
}